// round 10
// baseline (speedup 1.0000x reference)
#include <cuda_runtime.h>

typedef unsigned long long u64;

#define BT  256   // threads per block
#define XPT 2     // vectors per thread (keeps the fully-unrolled body ~43KB)
#define NP  128   // codeword pairs

// Packed codebook records: pair p = {ab0, ab1, cd0, cd1, q} (5 x u64 = 5KB)
__device__    u64 g_pack[NP * 5];
__constant__  u64 c_pack[NP * 5];

__device__ __forceinline__ u64 pk2(float lo, float hi) {
    u64 r;
    asm("mov.b64 %0, {%1, %2};" : "=l"(r) : "f"(lo), "f"(hi));
    return r;
}
__device__ __forceinline__ void upk2(u64 v, float& lo, float& hi) {
    asm("mov.b64 {%0, %1}, %2;" : "=f"(lo), "=f"(hi) : "l"(v));
}
// Blackwell packed fp32 FMA: d.lo = a.lo*b.lo + c.lo ; d.hi = a.hi*b.hi + c.hi
__device__ __forceinline__ u64 ffma2(u64 a, u64 b, u64 c) {
    u64 d;
    asm("fma.rn.f32x2 %0, %1, %2, %3;" : "=l"(d) : "l"(a), "l"(b), "l"(c));
    return d;
}
// ||c||^2 with a FIXED rounding order, used identically in pack and recovery.
__device__ __forceinline__ float qnorm(float4 a) {
    return __fmaf_rn(a.w, a.w, __fmaf_rn(a.z, a.z, __fmaf_rn(a.y, a.y, __fmul_rn(a.x, a.x))));
}

__global__ void pack_kernel(const float4* __restrict__ C) {
    const int t = threadIdx.x;
    if (t < NP) {
        float4 a = C[2 * t];
        float4 b = C[2 * t + 1];
        g_pack[5 * t + 0] = pk2(a.x, b.x);
        g_pack[5 * t + 1] = pk2(a.y, b.y);
        g_pack[5 * t + 2] = pk2(a.z, b.z);
        g_pack[5 * t + 3] = pk2(a.w, b.w);
        g_pack[5 * t + 4] = pk2(qnorm(a), qnorm(b));
    }
}

__global__ void __launch_bounds__(BT, 6)
vq_kernel(const float4* __restrict__ X,
          const float4* __restrict__ C,
          float4* __restrict__ outX,
          float* __restrict__ outS,
          int B)
{
    const int base = blockIdx.x * (BT * XPT) + threadIdx.x;

    u64 y0[XPT], y1[XPT], y2[XPT], y3[XPT];
    float bv[XPT];
    int   pid[XPT];

#pragma unroll
    for (int j = 0; j < XPT; j++) {
        int idx = base + j * BT;
        float4 x = (idx < B) ? X[idx] : make_float4(0.f, 0.f, 0.f, 0.f);
        float m0 = -2.0f * x.x, m1 = -2.0f * x.y, m2 = -2.0f * x.z, m3 = -2.0f * x.w;
        y0[j] = pk2(m0, m0);
        y1[j] = pk2(m1, m1);
        y2[j] = pk2(m2, m2);
        y3[j] = pk2(m3, m3);
        bv[j] = 3.402823466e38f;
        pid[j] = 0;
    }

    // Main loop: val_k = ||c_k||^2 - 2 x.c_k (same argmin as full distance).
    // FULLY unrolled: every c_pack access has a compile-time immediate offset, so
    // the codebook flows through the uniform-const path (LDCU -> UR) and the FFMA2
    // operands are R,R,UR,R — 2 even + 2 odd distinct GPRs -> rt=2 instead of 3.
#pragma unroll
    for (int p = 0; p < NP; p++) {
        const u64 ab0 = c_pack[5 * p + 0];
        const u64 ab1 = c_pack[5 * p + 1];
        const u64 cd0 = c_pack[5 * p + 2];
        const u64 cd1 = c_pack[5 * p + 3];
        const u64 q   = c_pack[5 * p + 4];
#pragma unroll
        for (int j = 0; j < XPT; j++) {
            u64 acc = ffma2(y0[j], ab0, q);
            acc = ffma2(y1[j], ab1, acc);
            acc = ffma2(y2[j], cd0, acc);
            acc = ffma2(y3[j], cd1, acc);
            float lo, hi;
            upk2(acc, lo, hi);
            float pv = fminf(lo, hi);
            if (pv < bv[j]) pid[j] = p;      // strict <: earlier pair wins ties
            bv[j] = fminf(bv[j], pv);        // FMNMX chain, lat 4
        }
    }

    // Recovery: reload the winning pair's raw rows from gmem (L1-resident, 8KB) and
    // replay the distance with a bitwise-identical scalar FFMA chain (lane semantics
    // of ffma2; q recomputed via the same qnorm used by pack_kernel -> bitwise equal).
    // hi<lo resolves the within-pair index; ties prefer lo (= smaller index),
    // matching jnp.argmin first-occurrence. Winner row doubles as the outX gather.
#pragma unroll
    for (int j = 0; j < XPT; j++) {
        const int p = pid[j];
        const float4 ca = C[2 * p];
        const float4 cb = C[2 * p + 1];
        const float qa = qnorm(ca);
        const float qb = qnorm(cb);
        float m0, m1, m2, m3, d_;
        upk2(y0[j], m0, d_); upk2(y1[j], m1, d_);
        upk2(y2[j], m2, d_); upk2(y3[j], m3, d_);
        float lo = __fmaf_rn(m3, ca.w, __fmaf_rn(m2, ca.z, __fmaf_rn(m1, ca.y, __fmaf_rn(m0, ca.x, qa))));
        float hi = __fmaf_rn(m3, cb.w, __fmaf_rn(m2, cb.z, __fmaf_rn(m1, cb.y, __fmaf_rn(m0, cb.x, qb))));
        const bool h = (hi < lo);
        const int idx = base + j * BT;
        if (idx < B) {
            outX[idx] = h ? cb : ca;
            outS[idx] = (float)(2 * p + (h ? 1 : 0));   // harness reads d_out as f32
        }
    }
}

extern "C" void kernel_launch(void* const* d_in, const int* in_sizes, int n_in,
                              void* d_out, int out_size)
{
    const float4* X = (const float4*)d_in[0];   // [B, 4] fp32
    const float4* C = (const float4*)d_in[1];   // [256, 4] fp32 codebook

    const int B = in_sizes[0] / 4;

    float4* outX = (float4*)d_out;                  // hatX [B,4] fp32
    float*  outS = (float*)d_out + 4 * (size_t)B;   // state [B] as fp32

    // 1) pack codebook pairs into a device buffer
    pack_kernel<<<1, 128>>>(C);

    // 2) stage packed records into the constant bank (D2D async, capturable)
    void* gp = nullptr;
    cudaGetSymbolAddress(&gp, g_pack);
    cudaMemcpyToSymbolAsync(c_pack, gp, sizeof(u64) * NP * 5, 0,
                            cudaMemcpyDeviceToDevice, 0);

    // 3) main kernel
    const int grid = (B + BT * XPT - 1) / (BT * XPT);
    vq_kernel<<<grid, BT>>>(X, C, outX, outS, B);
}

// round 11
// speedup vs baseline: 5.2442x; 5.2442x over previous
#include <cuda_runtime.h>

typedef unsigned long long u64;

#define BT  256   // threads per block
#define XPT 3     // vectors per thread
#define NP  128   // codeword pairs
#define CH  4     // pairs per chunk (8 codewords)
#define NC  (NP/CH)   // 32 chunks

__device__ __forceinline__ u64 pk2(float lo, float hi) {
    u64 r;
    asm("mov.b64 %0, {%1, %2};" : "=l"(r) : "f"(lo), "f"(hi));
    return r;
}
__device__ __forceinline__ void upk2(u64 v, float& lo, float& hi) {
    asm("mov.b64 {%0, %1}, %2;" : "=f"(lo), "=f"(hi) : "l"(v));
}
// Blackwell packed fp32 FMA: d.lo = a.lo*b.lo + c.lo ; d.hi = a.hi*b.hi + c.hi
__device__ __forceinline__ u64 ffma2(u64 a, u64 b, u64 c) {
    u64 d;
    asm("fma.rn.f32x2 %0, %1, %2, %3;" : "=l"(d) : "l"(a), "l"(b), "l"(c));
    return d;
}
// ||c||^2 with a FIXED IEEE op order — the ONLY way q is ever computed
// (smem fill and recovery both call this => bitwise-identical values).
__device__ __forceinline__ float qnorm(float4 a) {
    return __fmaf_rn(a.w, a.w, __fmaf_rn(a.z, a.z, __fmaf_rn(a.y, a.y, __fmul_rn(a.x, a.x))));
}

__global__ void __launch_bounds__(BT, 4)
vq_kernel(const float4* __restrict__ X,
          const float4* __restrict__ C,
          float4* __restrict__ outX,
          float* __restrict__ outS,
          int B)
{
    // Packed codebook: pair p covers codewords (2p, 2p+1)
    __shared__ ulonglong2 sAB[NP];      // (dim0 pair, dim1 pair)
    __shared__ ulonglong2 sCD[NP];      // (dim2 pair, dim3 pair)
    __shared__ ulonglong2 sQ2[NP / 2];  // ||c||^2 for pairs (2i,2i+1) in one 16B slot

    const int t = threadIdx.x;

    if (t < NP) {
        float4 a = C[2 * t];
        float4 b = C[2 * t + 1];
        sAB[t] = make_ulonglong2(pk2(a.x, b.x), pk2(a.y, b.y));
        sCD[t] = make_ulonglong2(pk2(a.z, b.z), pk2(a.w, b.w));
        u64 qp = pk2(qnorm(a), qnorm(b));
        if (t & 1) sQ2[t >> 1].y = qp; else sQ2[t >> 1].x = qp;
    }
    __syncthreads();

    const int base = blockIdx.x * (BT * XPT) + t;

    u64 y0[XPT], y1[XPT], y2[XPT], y3[XPT];
    float bv[XPT];
    int   cid[XPT];

#pragma unroll
    for (int j = 0; j < XPT; j++) {
        int idx = base + j * BT;
        float4 x = (idx < B) ? X[idx] : make_float4(0.f, 0.f, 0.f, 0.f);
        float m0 = -2.0f * x.x, m1 = -2.0f * x.y, m2 = -2.0f * x.z, m3 = -2.0f * x.w;
        y0[j] = pk2(m0, m0);
        y1[j] = pk2(m1, m1);
        y2[j] = pk2(m2, m2);
        y3[j] = pk2(m3, m3);
        bv[j] = 3.402823466e38f;
        cid[j] = 0;
    }

    // Main loop: val_k = ||c_k||^2 - 2 x.c_k (same argmin as full distance).
    // Chunk bookkeeping: per pair only 4 FFMA2 + 1 FMNMX; the setp/sel/min
    // triple runs once per 4-pair chunk on a 3-FMNMX tree of independent pv's.
#pragma unroll 2
    for (int c = 0; c < NC; c++) {
        float pv[CH][XPT];
#pragma unroll
        for (int i = 0; i < CH; i += 2) {
            const int p = c * CH + i;
            const ulonglong2 qq = sQ2[p >> 1];   // broadcast LDS, conflict-free
            {
                const ulonglong2 ab = sAB[p];
                const ulonglong2 cd = sCD[p];
#pragma unroll
                for (int j = 0; j < XPT; j++) {
                    u64 acc = ffma2(y0[j], ab.x, qq.x);
                    acc = ffma2(y1[j], ab.y, acc);
                    acc = ffma2(y2[j], cd.x, acc);
                    acc = ffma2(y3[j], cd.y, acc);
                    float lo, hi;
                    upk2(acc, lo, hi);
                    pv[i][j] = fminf(lo, hi);
                }
            }
            {
                const ulonglong2 ab = sAB[p + 1];
                const ulonglong2 cd = sCD[p + 1];
#pragma unroll
                for (int j = 0; j < XPT; j++) {
                    u64 acc = ffma2(y0[j], ab.x, qq.y);
                    acc = ffma2(y1[j], ab.y, acc);
                    acc = ffma2(y2[j], cd.x, acc);
                    acc = ffma2(y3[j], cd.y, acc);
                    float lo, hi;
                    upk2(acc, lo, hi);
                    pv[i + 1][j] = fminf(lo, hi);
                }
            }
        }
#pragma unroll
        for (int j = 0; j < XPT; j++) {
            float cm = fminf(fminf(pv[0][j], pv[1][j]),
                             fminf(pv[2][j], pv[3][j]));
            if (cm < bv[j]) cid[j] = c;      // strict <: earlier chunk wins ties
            bv[j] = fminf(bv[j], cm);        // FMNMX, lat 4
        }
    }

    // Recovery: replay the winning chunk (8 codewords) from gmem C (L1-resident,
    // 4KB) with scalar __fmaf_rn chains — bitwise identical to the ffma2 lanes,
    // q recomputed via the same qnorm used for smem. FMNMX returns an input
    // exactly, so d == bv is guaranteed for the winner. Descending scan with
    // overwrite => smallest index wins, matching jnp.argmin first-occurrence.
#pragma unroll
    for (int j = 0; j < XPT; j++) {
        const int pb = cid[j] * CH;
        float m0, m1, m2, m3, d_;
        upk2(y0[j], m0, d_); upk2(y1[j], m1, d_);
        upk2(y2[j], m2, d_); upk2(y3[j], m3, d_);
        int bi = 0;
#pragma unroll
        for (int i = CH - 1; i >= 0; i--) {
            const float4 ca = C[2 * (pb + i)];
            const float4 cb = C[2 * (pb + i) + 1];
            const float qa = qnorm(ca);
            const float qb = qnorm(cb);
            float lo = __fmaf_rn(m3, ca.w, __fmaf_rn(m2, ca.z,
                        __fmaf_rn(m1, ca.y, __fmaf_rn(m0, ca.x, qa))));
            float hi = __fmaf_rn(m3, cb.w, __fmaf_rn(m2, cb.z,
                        __fmaf_rn(m1, cb.y, __fmaf_rn(m0, cb.x, qb))));
            if (hi == bv[j]) bi = 2 * (pb + i) + 1;
            if (lo == bv[j]) bi = 2 * (pb + i);
        }
        const int idx = base + j * BT;
        if (idx < B) {
            outX[idx] = C[bi];               // L1 hit, 4KB codebook
            outS[idx] = (float)bi;           // harness reads d_out as float32
        }
    }
}

extern "C" void kernel_launch(void* const* d_in, const int* in_sizes, int n_in,
                              void* d_out, int out_size)
{
    const float4* X = (const float4*)d_in[0];   // [B, 4] fp32
    const float4* C = (const float4*)d_in[1];   // [256, 4] fp32 codebook

    const int B = in_sizes[0] / 4;

    float4* outX = (float4*)d_out;                  // hatX [B,4] fp32
    float*  outS = (float*)d_out + 4 * (size_t)B;   // state [B] as fp32

    const int grid = (B + BT * XPT - 1) / (BT * XPT);
    vq_kernel<<<grid, BT>>>(X, C, outX, outS, B);
}

// round 13
// speedup vs baseline: 5.2890x; 1.0085x over previous
#include <cuda_runtime.h>

typedef unsigned long long u64;

#define BT   256   // threads per block
#define XPT  2     // vectors per thread per tile
#define NP   128   // codeword pairs
#define TILE (BT * XPT)
#define GRID 912   // ~6 CTAs/SM persistent

__device__ __forceinline__ u64 pk2(float lo, float hi) {
    u64 r;
    asm("mov.b64 %0, {%1, %2};" : "=l"(r) : "f"(lo), "f"(hi));
    return r;
}
__device__ __forceinline__ void upk2(u64 v, float& lo, float& hi) {
    asm("mov.b64 {%0, %1}, %2;" : "=f"(lo), "=f"(hi) : "l"(v));
}
// Blackwell packed fp32 FMA (per-lane IEEE fma) — the binding pipe resource.
__device__ __forceinline__ u64 ffma2(u64 a, u64 b, u64 c) {
    u64 d;
    asm("fma.rn.f32x2 %0, %1, %2, %3;" : "=l"(d) : "l"(a), "l"(b), "l"(c));
    return d;
}
// ||c||^2 with a FIXED IEEE op order — the only way q is ever computed.
__device__ __forceinline__ float qnorm(float4 a) {
    return __fmaf_rn(a.w, a.w, __fmaf_rn(a.z, a.z, __fmaf_rn(a.y, a.y, __fmul_rn(a.x, a.x))));
}

__global__ void __launch_bounds__(BT, 6)
vq_kernel(const float4* __restrict__ X,
          const float4* __restrict__ C,
          float4* __restrict__ outX,
          float* __restrict__ outS,
          int B, int nTiles)
{
    // Packed codebook: pair p covers codewords (2p, 2p+1). Loaded ONCE per CTA.
    __shared__ ulonglong2 sAB[NP];      // (dim0 pair, dim1 pair)
    __shared__ ulonglong2 sCD[NP];      // (dim2 pair, dim3 pair)
    __shared__ ulonglong2 sQ2[NP / 2];  // ||c||^2 for pairs (2i,2i+1), one 16B slot

    const int t = threadIdx.x;

    if (t < NP) {
        float4 a = C[2 * t];
        float4 b = C[2 * t + 1];
        sAB[t] = make_ulonglong2(pk2(a.x, b.x), pk2(a.y, b.y));
        sCD[t] = make_ulonglong2(pk2(a.z, b.z), pk2(a.w, b.w));
        u64 qp = pk2(qnorm(a), qnorm(b));
        if (t & 1) sQ2[t >> 1].y = qp; else sQ2[t >> 1].x = qp;
    }
    __syncthreads();   // the ONLY sync — codebook is read-only hereafter

    // Persistent tile loop: grid-stride over tiles of TILE vectors.
    for (int tile = blockIdx.x; tile < nTiles; tile += GRID) {
        const int base = tile * TILE + t;

        u64 y0[XPT], y1[XPT], y2[XPT], y3[XPT];
        float bv[XPT];
        int   pid[XPT];

#pragma unroll
        for (int j = 0; j < XPT; j++) {
            int idx = base + j * BT;
            float4 x = (idx < B) ? X[idx] : make_float4(0.f, 0.f, 0.f, 0.f);
            float m0 = -2.0f * x.x, m1 = -2.0f * x.y, m2 = -2.0f * x.z, m3 = -2.0f * x.w;
            y0[j] = pk2(m0, m0);
            y1[j] = pk2(m1, m1);
            y2[j] = pk2(m2, m2);
            y3[j] = pk2(m3, m3);
            bv[j] = 3.402823466e38f;
            pid[j] = 0;
        }

        // val_k = ||c_k||^2 - 2 x.c_k (same argmin as full distance).
        // Per pair per vector: 4 FFMA2 (fma pipe, binding) + 4 short alu.
#pragma unroll 4
        for (int p2 = 0; p2 < NP / 2; p2++) {
            const ulonglong2 qq = sQ2[p2];   // broadcast LDS, conflict-free
            {
                const int p = 2 * p2;
                const ulonglong2 ab = sAB[p];
                const ulonglong2 cd = sCD[p];
#pragma unroll
                for (int j = 0; j < XPT; j++) {
                    u64 acc = ffma2(y0[j], ab.x, qq.x);
                    acc = ffma2(y1[j], ab.y, acc);
                    acc = ffma2(y2[j], cd.x, acc);
                    acc = ffma2(y3[j], cd.y, acc);
                    float lo, hi;
                    upk2(acc, lo, hi);
                    float pv = fminf(lo, hi);
                    if (pv < bv[j]) pid[j] = p;   // strict <: earlier pair wins ties
                    bv[j] = fminf(bv[j], pv);     // FMNMX, lat 4
                }
            }
            {
                const int p = 2 * p2 + 1;
                const ulonglong2 ab = sAB[p];
                const ulonglong2 cd = sCD[p];
#pragma unroll
                for (int j = 0; j < XPT; j++) {
                    u64 acc = ffma2(y0[j], ab.x, qq.y);
                    acc = ffma2(y1[j], ab.y, acc);
                    acc = ffma2(y2[j], cd.x, acc);
                    acc = ffma2(y3[j], cd.y, acc);
                    float lo, hi;
                    upk2(acc, lo, hi);
                    float pv = fminf(lo, hi);
                    if (pv < bv[j]) pid[j] = p;
                    bv[j] = fminf(bv[j], pv);
                }
            }
        }

        // Recovery: replay the winning pair's bitwise-identical FFMA2 chain
        // (3 divergent LDS per vector, once per tile). FMNMX returns an input
        // exactly, so hi<lo resolves the within-pair index; ties prefer lo
        // (= smaller index), matching jnp.argmin first-occurrence.
#pragma unroll
        for (int j = 0; j < XPT; j++) {
            const int p = pid[j];
            const ulonglong2 rab = sAB[p];
            const ulonglong2 rcd = sCD[p];
            const ulonglong2 rqq = sQ2[p >> 1];
            const u64 rq = (p & 1) ? rqq.y : rqq.x;
            u64 acc = ffma2(y0[j], rab.x, rq);
            acc = ffma2(y1[j], rab.y, acc);
            acc = ffma2(y2[j], rcd.x, acc);
            acc = ffma2(y3[j], rcd.y, acc);
            float lo, hi;
            upk2(acc, lo, hi);
            const bool h = (hi < lo);
            float a0, b0, a1, b1, a2, b2, a3, b3;
            upk2(rab.x, a0, b0); upk2(rab.y, a1, b1);
            upk2(rcd.x, a2, b2); upk2(rcd.y, a3, b3);
            const int idx = base + j * BT;
            if (idx < B) {
                outX[idx] = make_float4(h ? b0 : a0, h ? b1 : a1,
                                        h ? b2 : a2, h ? b3 : a3);
                outS[idx] = (float)(2 * p + (h ? 1 : 0));   // read back as f32
            }
        }
    }
}

extern "C" void kernel_launch(void* const* d_in, const int* in_sizes, int n_in,
                              void* d_out, int out_size)
{
    const float4* X = (const float4*)d_in[0];   // [B, 4] fp32
    const float4* C = (const float4*)d_in[1];   // [256, 4] fp32 codebook

    const int B = in_sizes[0] / 4;
    const int nTiles = (B + TILE - 1) / TILE;

    float4* outX = (float4*)d_out;                  // hatX [B,4] fp32
    float*  outS = (float*)d_out + 4 * (size_t)B;   // state [B] as fp32

    const int grid = (nTiles < GRID) ? nTiles : GRID;
    vq_kernel<<<grid, BT>>>(X, C, outX, outS, B, nTiles);
}